// round 1
// baseline (speedup 1.0000x reference)
#include <cuda_runtime.h>
#include <cuda_bf16.h>

#define N_STEPS   256
#define N_LORS    65536
#define IMG_ELEMS (128*128*128)

// ---------------------------------------------------------------------------
// Kernel 1: zero the accumulator (d_out doubles as the backprojection buffer)
// ---------------------------------------------------------------------------
__global__ void zero_kernel(float4* __restrict__ out) {
    int i = blockIdx.x * blockDim.x + threadIdx.x;
    out[i] = make_float4(0.f, 0.f, 0.f, 0.f);
}

// ---------------------------------------------------------------------------
// Kernel 2: warp-per-LOR forward + back projection.
//   lane l handles steps [8l, 8l+8): consecutive steps so same-voxel runs can
//   be merged in-register before atomicAdd.
// ---------------------------------------------------------------------------
__global__ __launch_bounds__(256)
void trace_kernel(const float* __restrict__ img,
                  const float* __restrict__ xl,
                  const float* __restrict__ yl,
                  const float* __restrict__ zl,
                  float* __restrict__ acc) {
    const int warp = blockIdx.x * (blockDim.x >> 5) + (threadIdx.x >> 5);
    const int lane = threadIdx.x & 31;
    const int set  = warp >> 16;          // 0,1,2
    const int lor  = warp & (N_LORS - 1);

    const float* lors = (set == 0) ? xl : (set == 1) ? yl : zl;
    const float* L = lors + 7 * lor;

    const float p1x = L[0], p1y = L[1], p1z = L[2];
    const float dx = L[3] - p1x, dy = L[4] - p1y, dz = L[5] - p1z;
    const float meas = L[6];
    const float seg = sqrtf(dx*dx + dy*dy + dz*dz) * (1.0f / N_STEPS);

    int   flats[8];
    float s = 0.f;

    #pragma unroll
    for (int j = 0; j < 8; j++) {
        const int   st = lane * 8 + j;
        const float t  = ((float)st + 0.5f) * (1.0f / N_STEPS);
        // Match reference op order: pos = p1 + t*(p2-p1); idx = floor((pos-low)/vox)
        const float px = p1x + t * dx;
        const float py = p1y + t * dy;
        const float pz = p1z + t * dz;
        const float fx = floorf((px + 150.0f) / 2.34375f);
        const float fy = floorf((py + 150.0f) / 2.34375f);
        const float fz = floorf((pz + 150.0f) / 2.34375f);
        const bool inb = (fx >= 0.f) && (fx < 128.f) &&
                         (fy >= 0.f) && (fy < 128.f) &&
                         (fz >= 0.f) && (fz < 128.f);
        if (inb) {
            const int flat = (((int)fx * 128 + (int)fy) << 7) + (int)fz;
            flats[j] = flat;
            s += __ldg(img + flat);
        } else {
            flats[j] = -1;
        }
    }

    // warp reduction of the forward projection
    #pragma unroll
    for (int o = 16; o > 0; o >>= 1)
        s += __shfl_xor_sync(0xffffffffu, s, o);

    const float proj = s * seg;
    const float w = meas / (proj + 1e-8f) * seg;   // ratio * seg (reference order)

    // backproject: merge consecutive same-voxel samples into one atomic
    int   runflat = -1;
    float runw = 0.f;
    #pragma unroll
    for (int j = 0; j < 8; j++) {
        const int f = flats[j];
        if (f == runflat) {
            runw += w;
        } else {
            if (runflat >= 0) atomicAdd(acc + runflat, runw);
            runflat = f;
            runw = w;
        }
    }
    if (runflat >= 0) atomicAdd(acc + runflat, runw);
}

// ---------------------------------------------------------------------------
// Kernel 3: out = image / (eff + eps) * acc   (in-place on d_out)
// ---------------------------------------------------------------------------
__global__ void finalize_kernel(const float4* __restrict__ img,
                                const float4* __restrict__ eff,
                                float4* __restrict__ out) {
    int i = blockIdx.x * blockDim.x + threadIdx.x;
    float4 a = img[i], e = eff[i], o = out[i];
    o.x = a.x / (e.x + 1e-8f) * o.x;
    o.y = a.y / (e.y + 1e-8f) * o.y;
    o.z = a.z / (e.z + 1e-8f) * o.z;
    o.w = a.w / (e.w + 1e-8f) * o.w;
    out[i] = o;
}

extern "C" void kernel_launch(void* const* d_in, const int* in_sizes, int n_in,
                              void* d_out, int out_size) {
    const float* image = (const float*)d_in[0];
    const float* eff   = (const float*)d_in[1];
    const float* xl    = (const float*)d_in[2];
    const float* yl    = (const float*)d_in[3];
    const float* zl    = (const float*)d_in[4];
    float* out = (float*)d_out;

    // zero accumulator (d_out)
    zero_kernel<<<IMG_ELEMS / 4 / 256, 256>>>((float4*)out);

    // 3 * 65536 LORs, one warp each, 8 warps per block
    const int total_warps = 3 * N_LORS;
    trace_kernel<<<total_warps / 8, 256>>>(image, xl, yl, zl, out);

    finalize_kernel<<<IMG_ELEMS / 4 / 256, 256>>>((const float4*)image,
                                                  (const float4*)eff,
                                                  (float4*)out);
}

// round 2
// speedup vs baseline: 1.1771x; 1.1771x over previous
#include <cuda_runtime.h>
#include <cuda_bf16.h>

#define N_STEPS   256
#define N_LORS    65536
#define IMG_ELEMS (128*128*128)

// ---------------------------------------------------------------------------
// Kernel 1: zero the accumulator (d_out doubles as the backprojection buffer)
// ---------------------------------------------------------------------------
__global__ void zero_kernel(float4* __restrict__ out) {
    int i = blockIdx.x * blockDim.x + threadIdx.x;
    out[i] = make_float4(0.f, 0.f, 0.f, 0.f);
}

// ---------------------------------------------------------------------------
// Kernel 2: warp-per-LOR forward + back projection.
//   Lane l handles steps [8l, 8l+8): consecutive steps, so same-voxel runs
//   are merged in-register for BOTH the forward gather (1 load per run) and
//   the backprojection (1 atomic per run).
//   Index math uses explicit non-contracted mul/add/div to be bit-exact with
//   the jax reference (separate multiply+add, IEEE division), so voxel
//   decisions match exactly.
// ---------------------------------------------------------------------------
__global__ __launch_bounds__(256)
void trace_kernel(const float* __restrict__ img,
                  const float* __restrict__ xl,
                  const float* __restrict__ yl,
                  const float* __restrict__ zl,
                  float* __restrict__ acc) {
    const int warp = blockIdx.x * (blockDim.x >> 5) + (threadIdx.x >> 5);
    const int lane = threadIdx.x & 31;
    const int set  = warp >> 16;          // 0,1,2
    const int lor  = warp & (N_LORS - 1);

    const float* lors = (set == 0) ? xl : (set == 1) ? yl : zl;
    const float* L = lors + 7 * lor;

    const float p1x = L[0], p1y = L[1], p1z = L[2];
    const float dx = __fadd_rn(L[3], -p1x);
    const float dy = __fadd_rn(L[4], -p1y);
    const float dz = __fadd_rn(L[5], -p1z);
    const float meas = L[6];
    const float seg = sqrtf(dx*dx + dy*dy + dz*dz) * (1.0f / N_STEPS);

    int   flats[8];

    #pragma unroll
    for (int j = 0; j < 8; j++) {
        const int   st = lane * 8 + j;
        // t = (st + 0.5)/256 : exact (division by power of two)
        const float t  = ((float)st + 0.5f) * (1.0f / N_STEPS);
        // pos = p1 + t*d with SEPARATE mul and add (no FMA), matching jax
        const float px = __fadd_rn(p1x, __fmul_rn(t, dx));
        const float py = __fadd_rn(p1y, __fmul_rn(t, dy));
        const float pz = __fadd_rn(p1z, __fmul_rn(t, dz));
        // idx = floor((pos - low)/vox), low = -150, vox = 2.34375 (exact consts)
        const float fx = floorf(__fdiv_rn(__fadd_rn(px, 150.0f), 2.34375f));
        const float fy = floorf(__fdiv_rn(__fadd_rn(py, 150.0f), 2.34375f));
        const float fz = floorf(__fdiv_rn(__fadd_rn(pz, 150.0f), 2.34375f));
        const bool inb = (fx >= 0.f) && (fx < 128.f) &&
                         (fy >= 0.f) && (fy < 128.f) &&
                         (fz >= 0.f) && (fz < 128.f);
        flats[j] = inb ? ((((int)fx * 128 + (int)fy) << 7) + (int)fz) : -1;
    }

    // Forward projection with run-dedup: one L2 gather per distinct-voxel run.
    float s = 0.f;
    float v = 0.f;
    int   prevf = -2;                 // sentinel != any flat and != -1
    #pragma unroll
    for (int j = 0; j < 8; j++) {
        const int f = flats[j];
        if (f != prevf) {
            v = (f >= 0) ? __ldg(img + f) : 0.f;
            prevf = f;
        }
        s += v;                       // adds 0 when out of bounds
    }

    // warp reduction of the forward projection
    #pragma unroll
    for (int o = 16; o > 0; o >>= 1)
        s += __shfl_xor_sync(0xffffffffu, s, o);

    const float proj = s * seg;
    const float w = meas / (proj + 1e-8f) * seg;   // ratio * seg (reference order)

    // backproject: one atomic per distinct-voxel run
    int   runflat = -1;
    float runw = 0.f;
    #pragma unroll
    for (int j = 0; j < 8; j++) {
        const int f = flats[j];
        if (f == runflat) {
            runw += w;
        } else {
            if (runflat >= 0) atomicAdd(acc + runflat, runw);
            runflat = f;
            runw = w;
        }
    }
    if (runflat >= 0) atomicAdd(acc + runflat, runw);
}

// ---------------------------------------------------------------------------
// Kernel 3: out = image / (eff + eps) * acc   (in-place on d_out)
// ---------------------------------------------------------------------------
__global__ void finalize_kernel(const float4* __restrict__ img,
                                const float4* __restrict__ eff,
                                float4* __restrict__ out) {
    int i = blockIdx.x * blockDim.x + threadIdx.x;
    float4 a = img[i], e = eff[i], o = out[i];
    o.x = a.x / (e.x + 1e-8f) * o.x;
    o.y = a.y / (e.y + 1e-8f) * o.y;
    o.z = a.z / (e.z + 1e-8f) * o.z;
    o.w = a.w / (e.w + 1e-8f) * o.w;
    out[i] = o;
}

extern "C" void kernel_launch(void* const* d_in, const int* in_sizes, int n_in,
                              void* d_out, int out_size) {
    const float* image = (const float*)d_in[0];
    const float* eff   = (const float*)d_in[1];
    const float* xl    = (const float*)d_in[2];
    const float* yl    = (const float*)d_in[3];
    const float* zl    = (const float*)d_in[4];
    float* out = (float*)d_out;

    zero_kernel<<<IMG_ELEMS / 4 / 256, 256>>>((float4*)out);

    const int total_warps = 3 * N_LORS;
    trace_kernel<<<total_warps / 8, 256>>>(image, xl, yl, zl, out);

    finalize_kernel<<<IMG_ELEMS / 4 / 256, 256>>>((const float4*)image,
                                                  (const float4*)eff,
                                                  (float4*)out);
}